// round 1
// baseline (speedup 1.0000x reference)
#include <cuda_runtime.h>

// L1Distance: out[i][j] = sum_d |x1[i,d] - x2[j,d]|   (mean-adjustment cancels)
// N1 = N2 = 2048, D = 64, fp32.

constexpr int D      = 64;
constexpr int TILE   = 128;   // output tile per block (128x128)
constexpr int DCHUNK = 32;    // d staged in two chunks -> static smem < 48KB
constexpr int STRIDE = 132;   // padded smem row stride (floats); 528B, 16B-aligned

__global__ __launch_bounds__(256, 2)
void l1dist_kernel(const float* __restrict__ x1, const float* __restrict__ x2,
                   float* __restrict__ out, int N2) {
    __shared__ __align__(16) float As[DCHUNK * STRIDE];  // As[d][row] = x1[i0+row][dc+d]
    __shared__ __align__(16) float Bs[DCHUNK * STRIDE];  // Bs[d][row] = x2[j0+row][dc+d]

    const int i0  = blockIdx.y * TILE;
    const int j0  = blockIdx.x * TILE;
    const int tid = (int)threadIdx.x;
    const int ty  = tid >> 4;   // 0..15
    const int tx  = tid & 15;   // 0..15

    float acc[8][8];
#pragma unroll
    for (int m = 0; m < 8; m++)
#pragma unroll
        for (int n = 0; n < 8; n++) acc[m][n] = 0.0f;

    for (int dc = 0; dc < D; dc += DCHUNK) {
        // ---- stage chunk: 128 rows x 32 d, transposed into smem ----
        // 4096 floats per tile = 1024 float4; 256 threads -> 4 float4 each
#pragma unroll
        for (int k = 0; k < 4; k++) {
            int idx = tid + k * 256;        // 0..1023
            int row = idx >> 3;             // 8 float4 per row-chunk
            int d4  = (idx & 7) << 2;       // 0,4,...,28
            float4 a = *(const float4*)(x1 + (size_t)(i0 + row) * D + dc + d4);
            As[(d4 + 0) * STRIDE + row] = a.x;
            As[(d4 + 1) * STRIDE + row] = a.y;
            As[(d4 + 2) * STRIDE + row] = a.z;
            As[(d4 + 3) * STRIDE + row] = a.w;
            float4 b = *(const float4*)(x2 + (size_t)(j0 + row) * D + dc + d4);
            Bs[(d4 + 0) * STRIDE + row] = b.x;
            Bs[(d4 + 1) * STRIDE + row] = b.y;
            Bs[(d4 + 2) * STRIDE + row] = b.z;
            Bs[(d4 + 3) * STRIDE + row] = b.w;
        }
        __syncthreads();

        // ---- compute: 8x8 register tile, rows ty*4+{0..3}, ty*4+64+{0..3};
        //      cols tx*4+{0..3}, tx*4+64+{0..3} ----
#pragma unroll 4
        for (int d = 0; d < DCHUNK; d++) {
            const float* as = &As[d * STRIDE];
            const float* bs = &Bs[d * STRIDE];
            float4 a0 = *(const float4*)(as + ty * 4);
            float4 a1 = *(const float4*)(as + ty * 4 + 64);
            float4 b0 = *(const float4*)(bs + tx * 4);
            float4 b1 = *(const float4*)(bs + tx * 4 + 64);
            float ra[8] = {a0.x, a0.y, a0.z, a0.w, a1.x, a1.y, a1.z, a1.w};
            float rb[8] = {b0.x, b0.y, b0.z, b0.w, b1.x, b1.y, b1.z, b1.w};
#pragma unroll
            for (int m = 0; m < 8; m++)
#pragma unroll
                for (int n = 0; n < 8; n++)
                    acc[m][n] += fabsf(ra[m] - rb[n]);
        }
        __syncthreads();
    }

    // ---- store: float4 per 4 adjacent columns ----
#pragma unroll
    for (int m = 0; m < 8; m++) {
        int r = i0 + ty * 4 + (m & 3) + ((m >> 2) << 6);
        float* orow = out + (size_t)r * N2 + j0 + tx * 4;
#pragma unroll
        for (int n4 = 0; n4 < 2; n4++) {
            float4 v = make_float4(acc[m][n4 * 4 + 0], acc[m][n4 * 4 + 1],
                                   acc[m][n4 * 4 + 2], acc[m][n4 * 4 + 3]);
            *(float4*)(orow + (n4 << 6)) = v;
        }
    }
}

extern "C" void kernel_launch(void* const* d_in, const int* in_sizes, int n_in,
                              void* d_out, int out_size) {
    const float* x1 = (const float*)d_in[0];
    const float* x2 = (const float*)d_in[1];
    float* out = (float*)d_out;

    int N1 = in_sizes[0] / D;   // 2048
    int N2 = in_sizes[1] / D;   // 2048

    dim3 grid(N2 / TILE, N1 / TILE);   // 16 x 16
    l1dist_kernel<<<grid, 256>>>(x1, x2, out, N2);
}